// round 3
// baseline (speedup 1.0000x reference)
#include <cuda_runtime.h>
#include <cuda_bf16.h>
#include <cstdint>

// NeRF emission-absorption raymarcher.
// Inputs (metadata order):
//   d_in[0]: rays_densities (B,R,N,1) float32   -> B*R*N elems
//   d_in[1]: rays_features  (B,R,N,F) float32   -> B*R*N*F elems
//   d_in[2]: lengths        (B,R,N)   float32   -> B*R*N elems
// Output: (B,R,F+1) float32, F=3 -> 4 floats per ray.
//
// One warp per ray-iteration. Lane i owns samples [4i, 4i+4).
// R3: persistent grid-stride kernel (152 SMs x 4 CTAs x 8 warps), explicit
// 2-ray double buffering -> 10 LDG.128 in flight per warp, no block churn.
// Streaming (evict-first) policy on all loads/stores: zero-reuse 335 MB stream.

#define EPS 1e-10f

struct RayBuf {
    float4 d4, l4, fa, fb, fc;
};

__device__ __forceinline__ void load_ray(RayBuf& b,
                                         const float* __restrict__ dens,
                                         const float* __restrict__ feat,
                                         const float* __restrict__ lens,
                                         int ray, int lane)
{
    const long long bn = (long long)ray * 128;
    const long long bf = (long long)ray * 384;
    b.d4 = __ldcs((const float4*)(dens + bn) + lane);
    b.l4 = __ldcs((const float4*)(lens + bn) + lane);
    const float4* fp = (const float4*)(feat + bf) + 3 * lane;
    b.fa = __ldcs(fp + 0);   // s0.xyz, s1.x
    b.fb = __ldcs(fp + 1);   // s1.yz,  s2.xy
    b.fc = __ldcs(fp + 2);   // s2.z,   s3.xyz
}

__device__ __forceinline__ void process_ray(const RayBuf& bu,
                                            float* __restrict__ out,
                                            int ray, int lane)
{
    // a_k = 1 + EPS - d_k
    const float a0 = 1.0f + EPS - bu.d4.x;
    const float a1 = 1.0f + EPS - bu.d4.y;
    const float a2 = 1.0f + EPS - bu.d4.z;
    const float a3 = 1.0f + EPS - bu.d4.w;

    // warp inclusive product scan of per-lane total product
    float incl = (a0 * a1) * (a2 * a3);
    #pragma unroll
    for (int off = 1; off < 32; off <<= 1) {
        float v = __shfl_up_sync(0xffffffffu, incl, off);
        if (lane >= off) incl *= v;
    }
    float excl = __shfl_up_sync(0xffffffffu, incl, 1);
    if (lane == 0) excl = 1.0f;

    const float ab0 = excl;
    const float ab1 = ab0 * a0;
    const float ab2 = ab1 * a1;
    const float ab3 = ab2 * a2;

    const float w0 = bu.d4.x * ab0;
    const float w1 = bu.d4.y * ab1;
    const float w2 = bu.d4.z * ab2;
    const float w3 = bu.d4.w * ab3;

    // feature unpack per sample:
    // s0: (fa.x, fa.y, fa.z)   s1: (fa.w, fb.x, fb.y)
    // s2: (fb.z, fb.w, fc.x)   s3: (fc.y, fc.z, fc.w)
    float r = w0 * bu.fa.x + w1 * bu.fa.w + w2 * bu.fb.z + w3 * bu.fc.y;
    float g = w0 * bu.fa.y + w1 * bu.fb.x + w2 * bu.fb.w + w3 * bu.fc.z;
    float b = w0 * bu.fa.z + w1 * bu.fb.y + w2 * bu.fc.x + w3 * bu.fc.w;

    float depth = w0 * bu.l4.x + w1 * bu.l4.y + w2 * bu.l4.z + w3 * bu.l4.w;
    float alpha = (w0 + w1) + (w2 + w3);

    #pragma unroll
    for (int off = 16; off > 0; off >>= 1) {
        r     += __shfl_down_sync(0xffffffffu, r,     off);
        g     += __shfl_down_sync(0xffffffffu, g,     off);
        b     += __shfl_down_sync(0xffffffffu, b,     off);
        depth += __shfl_down_sync(0xffffffffu, depth, off);
        alpha += __shfl_down_sync(0xffffffffu, alpha, off);
    }

    const float last_len = __shfl_sync(0xffffffffu, bu.l4.w, 31);

    if (lane == 0) {
        const float one_m_alpha = 1.0f - alpha;
        float4 o;
        o.x = r + one_m_alpha;                 // WHITE_BG
        o.y = g + one_m_alpha;
        o.z = b + one_m_alpha;
        o.w = depth + one_m_alpha * last_len;  // background depth fill
        __stcs((float4*)out + ray, o);
    }
}

__global__ __launch_bounds__(256, 4)
void ea_raymarch_kernel(const float* __restrict__ dens,
                        const float* __restrict__ feat,
                        const float* __restrict__ lens,
                        float* __restrict__ out,
                        int n_rays)
{
    const int wpb   = blockDim.x >> 5;
    const int nwarp = gridDim.x * wpb;                       // total warps
    const int w0    = blockIdx.x * wpb + (threadIdx.x >> 5); // this warp's id
    const int lane  = threadIdx.x & 31;

    for (int ray = w0; ray < n_rays; ray += 2 * nwarp) {
        RayBuf A, B;
        const int rayB = ray + nwarp;
        const bool hasB = rayB < n_rays;

        load_ray(A, dens, feat, lens, ray, lane);
        if (hasB) load_ray(B, dens, feat, lens, rayB, lane);

        process_ray(A, out, ray, lane);
        if (hasB) process_ray(B, out, rayB, lane);
    }
}

extern "C" void kernel_launch(void* const* d_in, const int* in_sizes, int n_in,
                              void* d_out, int out_size)
{
    const float* dens = (const float*)d_in[0];
    const float* feat = (const float*)d_in[1];
    const float* lens = (const float*)d_in[2];
    float* out = (float*)d_out;

    const int n_rays = out_size / 4;          // (F+1)=4 floats per ray

    const int threads = 256;                  // 8 warps/block
    // Persistent grid: 152 SMs x 4 CTAs (32 warps/SM at <=64 regs).
    int blocks = 152 * 4;
    const int wpb = threads / 32;
    const int max_blocks = (n_rays + wpb - 1) / wpb;   // never exceed work
    if (blocks > max_blocks) blocks = max_blocks;

    ea_raymarch_kernel<<<blocks, threads>>>(dens, feat, lens, out, n_rays);
}

// round 4
// speedup vs baseline: 1.1164x; 1.1164x over previous
#include <cuda_runtime.h>
#include <cuda_bf16.h>
#include <cstdint>

// NeRF emission-absorption raymarcher.
// Inputs (metadata order):
//   d_in[0]: rays_densities (B,R,N,1) float32   -> B*R*N elems
//   d_in[1]: rays_features  (B,R,N,F) float32   -> B*R*N*F elems
//   d_in[2]: lengths        (B,R,N)   float32   -> B*R*N elems
// Output: (B,R,F+1) float32, F=3 -> 4 floats per ray.
//
// One warp per ray. Lane i owns samples [4i, 4i+4). All loads are float4,
// consecutive lanes -> consecutive 16B -> fully coalesced, streaming policy.
// R4: 128-thread CTAs (vs 256) — finer scheduling granularity; regs=32 allows
// 16 CTAs/SM = full 64-warp occupancy with smoother pack/drain and smaller tail.
// (R3 lesson: warp count IS the MLP engine here — never trade occupancy for
// per-warp buffering on this kernel.)

#define EPS 1e-10f

__global__ __launch_bounds__(128, 16)
void ea_raymarch_kernel(const float* __restrict__ dens,
                        const float* __restrict__ feat,
                        const float* __restrict__ lens,
                        float* __restrict__ out,
                        int n_rays)
{
    const int warps_per_block = blockDim.x >> 5;
    const int ray = blockIdx.x * warps_per_block + (threadIdx.x >> 5);
    if (ray >= n_rays) return;
    const int lane = threadIdx.x & 31;

    // N = 128, F = 3 (fixed shapes for this problem)
    const long long base_n  = (long long)ray * 128;      // densities / lengths base (floats)
    const long long base_f  = (long long)ray * 384;      // features base (floats)

    // ---- loads: streaming (evict-first). densities first (scan depends on them) ----
    const float4 d4 = __ldcs((const float4*)(dens + base_n) + lane);
    const float4 l4 = __ldcs((const float4*)(lens + base_n) + lane);
    const float4* fptr = (const float4*)(feat + base_f) + 3 * lane;
    const float4 f4a = __ldcs(fptr + 0);   // s0.xyz, s1.x
    const float4 f4b = __ldcs(fptr + 1);   // s1.yz,  s2.xy
    const float4 f4c = __ldcs(fptr + 2);   // s2.z,   s3.xyz

    // a_k = 1 + EPS - d_k
    const float a0 = 1.0f + EPS - d4.x;
    const float a1 = 1.0f + EPS - d4.y;
    const float a2 = 1.0f + EPS - d4.z;
    const float a3 = 1.0f + EPS - d4.w;

    // warp inclusive product scan of per-lane total product
    float incl = (a0 * a1) * (a2 * a3);
    #pragma unroll
    for (int off = 1; off < 32; off <<= 1) {
        float v = __shfl_up_sync(0xffffffffu, incl, off);
        if (lane >= off) incl *= v;
    }
    // exclusive: shift by one lane
    float excl = __shfl_up_sync(0xffffffffu, incl, 1);
    if (lane == 0) excl = 1.0f;

    // per-sample absorptions and weights
    const float ab0 = excl;
    const float ab1 = ab0 * a0;
    const float ab2 = ab1 * a1;
    const float ab3 = ab2 * a2;

    const float w0 = d4.x * ab0;
    const float w1 = d4.y * ab1;
    const float w2 = d4.z * ab2;
    const float w3 = d4.w * ab3;

    // feature channel unpack per sample:
    // s0: (f4a.x, f4a.y, f4a.z)   s1: (f4a.w, f4b.x, f4b.y)
    // s2: (f4b.z, f4b.w, f4c.x)   s3: (f4c.y, f4c.z, f4c.w)
    float r = w0 * f4a.x + w1 * f4a.w + w2 * f4b.z + w3 * f4c.y;
    float g = w0 * f4a.y + w1 * f4b.x + w2 * f4b.w + w3 * f4c.z;
    float b = w0 * f4a.z + w1 * f4b.y + w2 * f4c.x + w3 * f4c.w;

    float depth = w0 * l4.x + w1 * l4.y + w2 * l4.z + w3 * l4.w;
    float alpha = (w0 + w1) + (w2 + w3);

    // warp reductions (sum) for the 5 accumulators
    #pragma unroll
    for (int off = 16; off > 0; off >>= 1) {
        r     += __shfl_down_sync(0xffffffffu, r,     off);
        g     += __shfl_down_sync(0xffffffffu, g,     off);
        b     += __shfl_down_sync(0xffffffffu, b,     off);
        depth += __shfl_down_sync(0xffffffffu, depth, off);
        alpha += __shfl_down_sync(0xffffffffu, alpha, off);
    }

    // last length along the ray = lane 31's l4.w
    const float last_len = __shfl_sync(0xffffffffu, l4.w, 31);

    if (lane == 0) {
        const float one_m_alpha = 1.0f - alpha;
        float4 o;
        o.x = r + one_m_alpha;                 // WHITE_BG
        o.y = g + one_m_alpha;
        o.z = b + one_m_alpha;
        o.w = depth + one_m_alpha * last_len;  // background depth fill
        __stcs((float4*)out + ray, o);
    }
}

extern "C" void kernel_launch(void* const* d_in, const int* in_sizes, int n_in,
                              void* d_out, int out_size)
{
    const float* dens = (const float*)d_in[0];
    const float* feat = (const float*)d_in[1];
    const float* lens = (const float*)d_in[2];
    float* out = (float*)d_out;

    // out_size = n_rays * (F+1) = n_rays * 4
    const int n_rays = out_size / 4;          // 131072 for this problem

    const int threads = 128;                  // 4 warps/block
    const int warps_per_block = threads / 32;
    const int blocks = (n_rays + warps_per_block - 1) / warps_per_block;

    ea_raymarch_kernel<<<blocks, threads>>>(dens, feat, lens, out, n_rays);
}